// round 7
// baseline (speedup 1.0000x reference)
#include <cuda_runtime.h>
#include <cuda_fp16.h>
#include <cstdint>

#define KDIM     4096
#define NDIM     16384
#define NSTAGES  3
#define SROW     40                  // ints per smem row (160B, conflict-free)
#define STAGE_I  (16 * SROW)         // 640 ints per warp-stage (2560 B)
#define WARP_I   (NSTAGES * STAGE_I) // 1920 ints per warp
#define NWARPS   24
#define SMEM_BYTES (NWARPS * WARP_I * 4)   // 184320 B

// X pre-packed to fp16 in mma-fragment order:
// XC[(kb*32 + lane)*8 + i], i order:
//   (g,lo)(g+8,lo)(g,hi)(g+8,hi)(g+16,lo)(g+24,lo)(g+16,hi)(g+24,hi)
__device__ uint32_t XC[(KDIM / 16) * 32 * 8];   // 256 KB

__device__ __forceinline__ void cp_async16(uint32_t dst, const void* src) {
    asm volatile("cp.async.cg.shared.global [%0], [%1], 16;" :: "r"(dst), "l"(src));
}
__device__ __forceinline__ void cp_commit() {
    asm volatile("cp.async.commit_group;");
}
template <int N>
__device__ __forceinline__ void cp_wait() {
    asm volatile("cp.async.wait_group %0;" :: "n"(N));
}

__device__ __forceinline__ uint32_t pack_h2(float hi, float lo) {
    uint32_t r;
    asm("cvt.rn.f16x2.f32 %0, %1, %2;" : "=r"(r) : "f"(hi), "f"(lo));
    return r;
}

// Exact int8 -> fp16 (no scale): byte -> fp16 magic (1152+v), subtract 1152.
// Both steps exact; result is the exact integer value as fp16.
__device__ __forceinline__ uint32_t dq(int2 w) {
    uint32_t r;
    asm("prmt.b32 %0, %1, %2, 0x0400;" : "=r"(r) : "r"(w.x), "r"(w.y));
    r = (r & 0x00FF00FFu) ^ 0x64806480u;
    __half2 h = __hsub2(*reinterpret_cast<__half2*>(&r),
                        __half2half2(__ushort_as_half((unsigned short)0x6480)));
    return *reinterpret_cast<uint32_t*>(&h);
}

__device__ __forceinline__ void mma16816(float c[4],
                                         uint32_t a0, uint32_t a1,
                                         uint32_t a2, uint32_t a3,
                                         uint32_t b0, uint32_t b1) {
    asm volatile(
        "mma.sync.aligned.m16n8k16.row.col.f32.f16.f16.f32 "
        "{%0,%1,%2,%3}, {%4,%5,%6,%7}, {%8,%9}, {%0,%1,%2,%3};"
        : "+f"(c[0]), "+f"(c[1]), "+f"(c[2]), "+f"(c[3])
        : "r"(a0), "r"(a1), "r"(a2), "r"(a3), "r"(b0), "r"(b1));
}

// ---------------- prologue kernel: pack X (f32, fp16-valued) into XC ----------------
__global__ void __launch_bounds__(256) convert_x_kernel(const float* __restrict__ X) {
    const int tid  = blockIdx.x * 256 + threadIdx.x;   // 8192 threads
    const int kb   = tid >> 5;
    const int lane = tid & 31;
    const int g    = lane >> 2;
    const int t    = lane & 3;
    const int c0   = kb * 16 + 2 * t;
    const int c1   = c0 + 8;

    uint32_t* dst = XC + (size_t)(kb * 32 + lane) * 8;
    const int r0 = g, r1 = g + 8, r2 = g + 16, r3 = g + 24;

    #define PK(r, c) pack_h2(X[(size_t)(r) * KDIM + (c) + 1], X[(size_t)(r) * KDIM + (c)])
    dst[0] = PK(r0, c0); dst[1] = PK(r1, c0); dst[2] = PK(r0, c1); dst[3] = PK(r1, c1);
    dst[4] = PK(r2, c0); dst[5] = PK(r3, c0); dst[6] = PK(r2, c1); dst[7] = PK(r3, c1);
    #undef PK
}

// ---------------- main GEMM: 24 warps, warp trios split k mod 3 ----------------
extern __shared__ int smem[];

__global__ void __launch_bounds__(768, 1)
w8linear_kernel(const int*   __restrict__ W,   // [16384, 4096] int32 (int8-valued)
                const float* __restrict__ S,   // [16384] f32 (fp16-valued)
                const float* __restrict__ Bi,  // [16384] f32 (fp16-valued)
                float*       __restrict__ O)   // [32, 16384] f32
{
    const int tid  = threadIdx.x;
    const int warp = tid >> 5;
    const int lane = tid & 31;
    const int g    = lane >> 2;
    const int t    = lane & 3;
    const int fg   = warp / 3;        // feature group 0..7
    const int par  = warp - fg * 3;   // k residue 0..2

    const int nbase = blockIdx.x * 128 + fg * 16;

    // per-warp smem ring
    int* const wsm = smem + warp * WARP_I;
    const uint32_t wsm_u32 = (uint32_t)__cvta_generic_to_shared(wsm);

    // producer mapping: lane -> row (lane>>1), 64B half (lane&1); 4 cp.async16/thread
    const int prow = lane >> 1;
    const int phal = lane & 1;
    const int* const gsrc = W + (size_t)(nbase + prow) * KDIM + phal * 16;
    const uint32_t sdst = wsm_u32 + (uint32_t)(prow * SROW + phal * 16) * 4;

    auto issue_stage = [&](int slot, int chunk) {
        const int*     src = gsrc + chunk * 32;
        const uint32_t dst = sdst + (uint32_t)(slot * STAGE_I) * 4;
#pragma unroll
        for (int j = 0; j < 4; j++)
            cp_async16(dst + j * 16, src + j * 4);
    };

    float acc[2][2][4];
#pragma unroll
    for (int mt = 0; mt < 2; mt++)
#pragma unroll
        for (int nt = 0; nt < 2; nt++)
#pragma unroll
            for (int i = 0; i < 4; i++) acc[mt][nt][i] = 0.0f;

    const int srow0 = g * SROW + 2 * t;
    const int srow1 = (8 + g) * SROW + 2 * t;

    // A register double-buffer: [buf][substep][mtile]
    uint4 Ab[2][2][2];
    auto load_A = [&](int buf, int chunk) {
#pragma unroll
        for (int s_ = 0; s_ < 2; s_++) {
            const uint32_t* ap = XC + (size_t)((chunk * 2 + s_) * 32 + lane) * 8;
            Ab[buf][s_][0] = __ldg((const uint4*)ap);
            Ab[buf][s_][1] = __ldg((const uint4*)(ap + 4));
        }
    };

    auto compute_chunk = [&](int slot, int buf) {
        const int sbase = slot * STAGE_I;
#pragma unroll
        for (int s_ = 0; s_ < 2; s_++) {
            const int koff = s_ * 16;
            const int2 w00 = *(const int2*)&wsm[sbase + srow0 + koff];
            const int2 w01 = *(const int2*)&wsm[sbase + srow0 + koff + 8];
            const int2 w10 = *(const int2*)&wsm[sbase + srow1 + koff];
            const int2 w11 = *(const int2*)&wsm[sbase + srow1 + koff + 8];

            const uint32_t b00 = dq(w00);
            const uint32_t b01 = dq(w01);
            const uint32_t b10 = dq(w10);
            const uint32_t b11 = dq(w11);

            const uint4 p0 = Ab[buf][s_][0];
            const uint4 p1 = Ab[buf][s_][1];
            mma16816(acc[0][0], p0.x, p0.y, p0.z, p0.w, b00, b01);
            mma16816(acc[0][1], p0.x, p0.y, p0.z, p0.w, b10, b11);
            mma16816(acc[1][0], p1.x, p1.y, p1.z, p1.w, b00, b01);
            mma16816(acc[1][1], p1.x, p1.y, p1.z, p1.w, b10, b11);
        }
    };

    // this warp's chunk list: c = par + 3*i
    const int niter = (par < 2) ? 43 : 42;   // 43+43+42 = 128

    // prologue: fill NSTAGES-1 = 2 stages
#pragma unroll
    for (int s = 0; s < NSTAGES - 1; s++) {
        issue_stage(s, par + 3 * s);
        cp_commit();
    }
    load_A(0, par);

    // main loop: warp-autonomous, no __syncthreads
    int slot_c = 0, slot_p = NSTAGES - 1;
#pragma unroll 2
    for (int i = 0; i < niter; i++) {
        const int buf = i & 1;

        cp_wait<NSTAGES - 2>();
        __syncwarp();

        if (i + NSTAGES - 1 < niter) issue_stage(slot_p, par + 3 * (i + NSTAGES - 1));
        cp_commit();

        if (i + 1 < niter) load_A(buf ^ 1, par + 3 * (i + 1));

        compute_chunk(slot_c, buf);

        slot_c = (slot_c + 1 == NSTAGES) ? 0 : slot_c + 1;
        slot_p = (slot_p + 1 == NSTAGES) ? 0 : slot_p + 1;
    }

    // ---- trio reduction: par 1,2 dump f32 accs into own ring space ----
    float* const afl = &acc[0][0][0];
    if (par != 0) {
        float* dst = (float*)wsm;
#pragma unroll
        for (int i = 0; i < 16; i++) dst[lane * 16 + i] = afl[i];
    }
    __syncthreads();

    if (par == 0) {
        const float* src1 = (const float*)(smem + (warp + 1) * WARP_I);
        const float* src2 = (const float*)(smem + (warp + 2) * WARP_I);
#pragma unroll
        for (int i = 0; i < 16; i++)
            afl[i] += src1[lane * 16 + i] + src2[lane * 16 + i];

        // epilogue: apply per-feature scale, then fp16 round + fp16 bias (ref rounding)
#pragma unroll
        for (int mt = 0; mt < 2; mt++) {
#pragma unroll
            for (int nt = 0; nt < 2; nt++) {
                const int f  = nbase + nt * 8 + 2 * t;
                const int r0 = mt * 16 + g;
                const int r1 = r0 + 8;
                const float sx = S[f];
                const float sy = S[f + 1];
                const __half bx = __float2half_rn(Bi[f]);
                const __half by = __float2half_rn(Bi[f + 1]);

                const __half h00 = __hadd(__float2half_rn(acc[mt][nt][0] * sx), bx);
                const __half h01 = __hadd(__float2half_rn(acc[mt][nt][1] * sy), by);
                const __half h10 = __hadd(__float2half_rn(acc[mt][nt][2] * sx), bx);
                const __half h11 = __hadd(__float2half_rn(acc[mt][nt][3] * sy), by);

                *(float2*)(O + (size_t)r0 * NDIM + f) =
                    make_float2(__half2float(h00), __half2float(h01));
                *(float2*)(O + (size_t)r1 * NDIM + f) =
                    make_float2(__half2float(h10), __half2float(h11));
            }
        }
    }
}

extern "C" void kernel_launch(void* const* d_in, const int* in_sizes, int n_in,
                              void* d_out, int out_size) {
    (void)in_sizes; (void)n_in; (void)out_size;
    const float* x = (const float*)d_in[0];
    const int*   w = (const int*)d_in[1];
    const float* s = (const float*)d_in[2];
    const float* b = (const float*)d_in[3];
    float*       o = (float*)d_out;

    convert_x_kernel<<<32, 256>>>(x);

    cudaFuncSetAttribute(w8linear_kernel,
                         cudaFuncAttributeMaxDynamicSharedMemorySize, SMEM_BYTES);
    w8linear_kernel<<<NDIM / 128, 768, SMEM_BYTES>>>(w, s, b, o);
}

// round 8
// speedup vs baseline: 1.2160x; 1.2160x over previous
#include <cuda_runtime.h>
#include <cuda_fp16.h>
#include <cstdint>

#define KDIM     4096
#define NDIM     16384
#define NSTAGES  3
#define SROW     40                   // ints per smem row (160B, conflict-free LDS phases)
#define NROWS    32                   // weight rows per warp-stage
#define STAGE_I  (NROWS * SROW)       // 1280 ints per warp-stage (5120 B)
#define WARP_I   (NSTAGES * STAGE_I)  // 3840 ints per warp
#define NWARPS   12
#define SMEM_BYTES (NWARPS * WARP_I * 4)   // 184320 B

// X pre-packed to fp16 in mma-fragment order:
// XC[(kb*32 + lane)*8 + i], i order:
//   (g,lo)(g+8,lo)(g,hi)(g+8,hi)(g+16,lo)(g+24,lo)(g+16,hi)(g+24,hi)
__device__ uint32_t XC[(KDIM / 16) * 32 * 8];   // 256 KB

__device__ __forceinline__ void cp_async16(uint32_t dst, const void* src) {
    asm volatile("cp.async.cg.shared.global [%0], [%1], 16;" :: "r"(dst), "l"(src));
}
__device__ __forceinline__ void cp_commit() {
    asm volatile("cp.async.commit_group;");
}
template <int N>
__device__ __forceinline__ void cp_wait() {
    asm volatile("cp.async.wait_group %0;" :: "n"(N));
}

__device__ __forceinline__ uint32_t pack_h2(float hi, float lo) {
    uint32_t r;
    asm("cvt.rn.f16x2.f32 %0, %1, %2;" : "=r"(r) : "f"(hi), "f"(lo));
    return r;
}

// Exact int8 -> fp16 (no scale): byte -> fp16 magic (1152+v), subtract 1152. Exact.
__device__ __forceinline__ uint32_t dq(int2 w) {
    uint32_t r;
    asm("prmt.b32 %0, %1, %2, 0x0400;" : "=r"(r) : "r"(w.x), "r"(w.y));
    r = (r & 0x00FF00FFu) ^ 0x64806480u;
    __half2 h = __hsub2(*reinterpret_cast<__half2*>(&r),
                        __half2half2(__ushort_as_half((unsigned short)0x6480)));
    return *reinterpret_cast<uint32_t*>(&h);
}

__device__ __forceinline__ void mma16816(float c[4],
                                         uint32_t a0, uint32_t a1,
                                         uint32_t a2, uint32_t a3,
                                         uint32_t b0, uint32_t b1) {
    asm volatile(
        "mma.sync.aligned.m16n8k16.row.col.f32.f16.f16.f32 "
        "{%0,%1,%2,%3}, {%4,%5,%6,%7}, {%8,%9}, {%0,%1,%2,%3};"
        : "+f"(c[0]), "+f"(c[1]), "+f"(c[2]), "+f"(c[3])
        : "r"(a0), "r"(a1), "r"(a2), "r"(a3), "r"(b0), "r"(b1));
}

// ---------------- prologue kernel: pack X (f32, fp16-valued) into XC ----------------
__global__ void __launch_bounds__(256) convert_x_kernel(const float* __restrict__ X) {
    const int tid  = blockIdx.x * 256 + threadIdx.x;   // 8192 threads
    const int kb   = tid >> 5;
    const int lane = tid & 31;
    const int g    = lane >> 2;
    const int t    = lane & 3;
    const int c0   = kb * 16 + 2 * t;
    const int c1   = c0 + 8;

    uint32_t* dst = XC + (size_t)(kb * 32 + lane) * 8;
    const int r0 = g, r1 = g + 8, r2 = g + 16, r3 = g + 24;

    #define PK(r, c) pack_h2(X[(size_t)(r) * KDIM + (c) + 1], X[(size_t)(r) * KDIM + (c)])
    dst[0] = PK(r0, c0); dst[1] = PK(r1, c0); dst[2] = PK(r0, c1); dst[3] = PK(r1, c1);
    dst[4] = PK(r2, c0); dst[5] = PK(r3, c0); dst[6] = PK(r2, c1); dst[7] = PK(r3, c1);
    #undef PK
}

// ---------------- main GEMM: 12 warps, 32 features/warp, k split 3 ways ----------------
extern __shared__ int smem[];

__global__ void __launch_bounds__(384, 1)
w8linear_kernel(const int*   __restrict__ W,   // [16384, 4096] int32 (int8-valued)
                const float* __restrict__ S,   // [16384] f32 (fp16-valued)
                const float* __restrict__ Bi,  // [16384] f32 (fp16-valued)
                float*       __restrict__ O)   // [32, 16384] f32
{
    const int tid  = threadIdx.x;
    const int warp = tid >> 5;
    const int lane = tid & 31;
    const int g    = lane >> 2;
    const int t    = lane & 3;
    const int fg   = warp >> 2;            // wrong for 12 warps? no: use /3 below
    (void)fg;
    const int fgrp = warp / 3;             // feature group 0..3 (32 features each)
    const int par  = warp - fgrp * 3;      // k residue 0..2

    const int nbase = blockIdx.x * 128 + fgrp * 32;

    // per-warp smem ring
    int* const wsm = smem + warp * WARP_I;
    const uint32_t wsm_u32 = (uint32_t)__cvta_generic_to_shared(wsm);

    // producer: op j copies rows 4j..4j+3; lane -> row 4j + (lane>>3), 16B seg (lane&7)
    const int prow = lane >> 3;            // 0..3
    const int pseg = lane & 7;             // 0..7
    const int* const gsrc = W + (size_t)(nbase + prow) * KDIM + pseg * 4;
    const uint32_t sdst = wsm_u32 + (uint32_t)(prow * SROW + pseg * 4) * 4;

    auto issue_stage = [&](int slot, int chunk) {
        const int*     src = gsrc + chunk * 32;
        const uint32_t dst = sdst + (uint32_t)(slot * STAGE_I) * 4;
#pragma unroll
        for (int j = 0; j < 8; j++)
            cp_async16(dst + (uint32_t)j * (4 * SROW * 4), src + (size_t)j * 4 * KDIM);
    };

    float acc[2][4][4];                    // [m-tile][n-tile][frag]
#pragma unroll
    for (int mt = 0; mt < 2; mt++)
#pragma unroll
        for (int nt = 0; nt < 4; nt++)
#pragma unroll
            for (int i = 0; i < 4; i++) acc[mt][nt][i] = 0.0f;

    // consumer smem row bases per n-tile
    int srow[4];
#pragma unroll
    for (int nt = 0; nt < 4; nt++) srow[nt] = (nt * 8 + g) * SROW + 2 * t;

    // A register double-buffer: [buf][substep][m-tile]
    uint4 Ab[2][2][2];
    auto load_A = [&](int buf, int chunk) {
#pragma unroll
        for (int s_ = 0; s_ < 2; s_++) {
            const uint32_t* ap = XC + (size_t)((chunk * 2 + s_) * 32 + lane) * 8;
            Ab[buf][s_][0] = __ldg((const uint4*)ap);
            Ab[buf][s_][1] = __ldg((const uint4*)(ap + 4));
        }
    };

    auto compute_chunk = [&](int slot, int buf) {
        const int sbase = slot * STAGE_I;
#pragma unroll
        for (int s_ = 0; s_ < 2; s_++) {
            const int koff = s_ * 16;
            const uint4 p0 = Ab[buf][s_][0];
            const uint4 p1 = Ab[buf][s_][1];
#pragma unroll
            for (int nt = 0; nt < 4; nt++) {
                const int2 w0 = *(const int2*)&wsm[sbase + srow[nt] + koff];
                const int2 w1 = *(const int2*)&wsm[sbase + srow[nt] + koff + 8];
                const uint32_t b0 = dq(w0);
                const uint32_t b1 = dq(w1);
                mma16816(acc[0][nt], p0.x, p0.y, p0.z, p0.w, b0, b1);
                mma16816(acc[1][nt], p1.x, p1.y, p1.z, p1.w, b0, b1);
            }
        }
    };

    const int niter = (par < 2) ? 43 : 42;   // 43+43+42 = 128 chunks

    // prologue: fill 2 stages
#pragma unroll
    for (int s = 0; s < NSTAGES - 1; s++) {
        issue_stage(s, par + 3 * s);
        cp_commit();
    }
    load_A(0, par);

    // main loop: warp-autonomous
    int slot_c = 0, slot_p = NSTAGES - 1;
#pragma unroll 2
    for (int i = 0; i < niter; i++) {
        const int buf = i & 1;

        cp_wait<NSTAGES - 2>();
        __syncwarp();

        if (i + NSTAGES - 1 < niter) issue_stage(slot_p, par + 3 * (i + NSTAGES - 1));
        cp_commit();

        if (i + 1 < niter) load_A(buf ^ 1, par + 3 * (i + 1));

        compute_chunk(slot_c, buf);

        slot_c = (slot_c + 1 == NSTAGES) ? 0 : slot_c + 1;
        slot_p = (slot_p + 1 == NSTAGES) ? 0 : slot_p + 1;
    }

    // ---- trio reduction: par 1,2 dump f32 accs into own ring space ----
    float* const afl = &acc[0][0][0];
    if (par != 0) {
        float* dst = (float*)wsm;
#pragma unroll
        for (int i = 0; i < 32; i++) dst[lane * 32 + i] = afl[i];
    }
    __syncthreads();

    if (par == 0) {
        const float* src1 = (const float*)(smem + (warp + 1) * WARP_I);
        const float* src2 = (const float*)(smem + (warp + 2) * WARP_I);
#pragma unroll
        for (int i = 0; i < 32; i++)
            afl[i] += src1[lane * 32 + i] + src2[lane * 32 + i];

        // epilogue: scale, fp16 round, add fp16 bias (reference rounding), store f32
#pragma unroll
        for (int mt = 0; mt < 2; mt++) {
#pragma unroll
            for (int nt = 0; nt < 4; nt++) {
                const int f  = nbase + nt * 8 + 2 * t;
                const int r0 = mt * 16 + g;
                const int r1 = r0 + 8;
                const float sx = S[f];
                const float sy = S[f + 1];
                const __half bx = __float2half_rn(Bi[f]);
                const __half by = __float2half_rn(Bi[f + 1]);

                const __half h00 = __hadd(__float2half_rn(acc[mt][nt][0] * sx), bx);
                const __half h01 = __hadd(__float2half_rn(acc[mt][nt][1] * sy), by);
                const __half h10 = __hadd(__float2half_rn(acc[mt][nt][2] * sx), bx);
                const __half h11 = __hadd(__float2half_rn(acc[mt][nt][3] * sy), by);

                *(float2*)(O + (size_t)r0 * NDIM + f) =
                    make_float2(__half2float(h00), __half2float(h01));
                *(float2*)(O + (size_t)r1 * NDIM + f) =
                    make_float2(__half2float(h10), __half2float(h11));
            }
        }
    }
}

extern "C" void kernel_launch(void* const* d_in, const int* in_sizes, int n_in,
                              void* d_out, int out_size) {
    (void)in_sizes; (void)n_in; (void)out_size;
    const float* x = (const float*)d_in[0];
    const int*   w = (const int*)d_in[1];
    const float* s = (const float*)d_in[2];
    const float* b = (const float*)d_in[3];
    float*       o = (float*)d_out;

    convert_x_kernel<<<32, 256>>>(x);

    cudaFuncSetAttribute(w8linear_kernel,
                         cudaFuncAttributeMaxDynamicSharedMemorySize, SMEM_BYTES);
    w8linear_kernel<<<NDIM / 128, 384, SMEM_BYTES>>>(w, s, b, o);
}